// round 4
// baseline (speedup 1.0000x reference)
#include <cuda_runtime.h>

#define NN 100000
#define EE 1200000
#define DD 64
#define DV (DD/4)   // 16 float4 per node row

// ---- scratch (static device globals; no allocation at runtime) ----
__device__ int    g_is64;
__device__ float  g_deg [NN];
__device__ float  g_dinv[NN];
__device__ float  g_ew  [EE];
__device__ int    g_row [EE];
__device__ int    g_col [EE];
__device__ float4 g_xA  [NN * DV];
__device__ float4 g_xB  [NN * DV];
__device__ float4 g_out [NN * DV];

// ---- kernels ----

// Detect whether the edge_index buffer is int64 or int32.
// If int64 (ids < 2^31), every odd int32 word (high half) is 0.
__global__ void detect_kernel(const int* __restrict__ ei32) {
    int s = 0;
    #pragma unroll 8
    for (int i = 0; i < 512; ++i) s |= ei32[2 * i + 1];
    g_is64 = (s == 0) ? 1 : 0;
}

__global__ void zero_deg_kernel() {
    int n = blockIdx.x * blockDim.x + threadIdx.x;
    if (n < NN) g_deg[n] = 0.0f;
}

__global__ void zero_x_kernel(float4* __restrict__ x) {
    int i = blockIdx.x * blockDim.x + threadIdx.x;
    if (i < NN * DV) x[i] = make_float4(0.f, 0.f, 0.f, 0.f);
}

// decode edge_index into int32 row/col and count in-degree of col
__global__ void prep_edges_kernel(const void* __restrict__ ei) {
    int e = blockIdx.x * blockDim.x + threadIdx.x;
    if (e < EE) {
        int r, c;
        if (g_is64) {
            const long long* p = (const long long*)ei;
            r = (int)p[e];
            c = (int)p[EE + e];
        } else {
            const int* p = (const int*)ei;
            r = p[e];
            c = p[EE + e];
        }
        // bounds guard: wrong decode -> wrong answer (diagnosable), not a fault
        if ((unsigned)r >= NN) r = 0;
        if ((unsigned)c >= NN) c = 0;
        g_row[e] = r;
        g_col[e] = c;
        atomicAdd(&g_deg[c], 1.0f);
    }
}

__global__ void dinv_kernel() {
    int n = blockIdx.x * blockDim.x + threadIdx.x;
    if (n < NN) {
        float d = g_deg[n];
        g_dinv[n] = (d > 0.0f) ? rsqrtf(d) : 0.0f;
    }
}

__global__ void edgew_kernel() {
    int e = blockIdx.x * blockDim.x + threadIdx.x;
    if (e < EE) {
        g_ew[e] = g_dinv[g_row[e]] * g_dinv[g_col[e]];
    }
}

// out = alpha[0] * w ; xA = w
__global__ void init_kernel(const float4* __restrict__ w,
                            const float* __restrict__ alpha) {
    int i = blockIdx.x * blockDim.x + threadIdx.x;
    if (i < NN * DV) {
        float a = alpha[0];
        float4 v = w[i];
        g_xA[i] = v;
        g_out[i] = make_float4(a * v.x, a * v.y, a * v.z, a * v.w);
    }
}

// dst[col] += ew * src[row]   (dst pre-zeroed)
// 16 consecutive threads handle one edge's 64-float row (float4 each)
__global__ void scatter_kernel(const float4* __restrict__ src,
                               float4* __restrict__ dst) {
    int idx = blockIdx.x * blockDim.x + threadIdx.x;   // < EE*16 exactly
    int e = idx >> 4;
    int c = idx & 15;
    float w = g_ew[e];
    int r  = g_row[e];
    int cl = g_col[e];
    float4 v = src[r * DV + c];
    float* d = (float*)&dst[cl * DV + c];
    atomicAdd(d + 0, w * v.x);
    atomicAdd(d + 1, w * v.y);
    atomicAdd(d + 2, w * v.z);
    atomicAdd(d + 3, w * v.w);
}

// out += alpha[k] * x
__global__ void axpy_kernel(const float4* __restrict__ x,
                            const float* __restrict__ alpha, int k) {
    int i = blockIdx.x * blockDim.x + threadIdx.x;
    if (i < NN * DV) {
        float a = alpha[k];
        float4 v = x[i];
        float4 o = g_out[i];
        o.x += a * v.x; o.y += a * v.y; o.z += a * v.z; o.w += a * v.w;
        g_out[i] = o;
    }
}

// per-edge dot(out[row], out[col]) with 16 lanes per edge
__global__ void dot_kernel(float* __restrict__ res) {
    int t = blockIdx.x * blockDim.x + threadIdx.x;     // < EE*16 exactly
    int e = t >> 4;
    int c = t & 15;
    int r  = g_row[e];
    int cl = g_col[e];
    float4 a = g_out[r * DV + c];
    float4 b = g_out[cl * DV + c];
    float s = a.x * b.x + a.y * b.y + a.z * b.z + a.w * b.w;
    s += __shfl_down_sync(0xffffffffu, s, 8);
    s += __shfl_down_sync(0xffffffffu, s, 4);
    s += __shfl_down_sync(0xffffffffu, s, 2);
    s += __shfl_down_sync(0xffffffffu, s, 1);
    if (c == 0) res[e] = s;
}

// ---- launch ----
extern "C" void kernel_launch(void* const* d_in, const int* in_sizes, int n_in,
                              void* d_out, int out_size) {
    // Bind inputs by element count (robust to metadata ordering):
    //   edge_index: 2*EE = 2,400,000 (int32 OR int64 -- detected on device)
    //   weight:     NN*DD = 6,400,000 (f32)
    //   alpha:      K+1 = 4 (f32)
    const void*  ei    = nullptr;
    const float* w     = nullptr;
    const float* alpha = nullptr;
    for (int i = 0; i < n_in; ++i) {
        if (in_sizes[i] == 2 * EE)       ei    = d_in[i];
        else if (in_sizes[i] == NN * DD) w     = (const float*)d_in[i];
        else if (in_sizes[i] == 4)       alpha = (const float*)d_in[i];
    }
    float* res = (float*)d_out;

    void *p_xA, *p_xB;
    cudaGetSymbolAddress(&p_xA, g_xA);
    cudaGetSymbolAddress(&p_xB, g_xB);

    const int T = 256;
    const int gE   = (EE + T - 1) / T;
    const int gN   = (NN + T - 1) / T;
    const int gND  = (NN * DV + T - 1) / T;
    const int gE16 = (EE * 16) / T;   // exact: 1.2M*16/256 = 75000

    detect_kernel<<<1, 1>>>((const int*)ei);
    zero_deg_kernel<<<gN, T>>>();
    prep_edges_kernel<<<gE, T>>>(ei);
    dinv_kernel<<<gN, T>>>();
    edgew_kernel<<<gE, T>>>();
    init_kernel<<<gND, T>>>((const float4*)w, alpha);

    float4* src = (float4*)p_xA;
    float4* dst = (float4*)p_xB;
    for (int k = 1; k <= 3; ++k) {
        zero_x_kernel<<<gND, T>>>(dst);
        scatter_kernel<<<gE16, T>>>(src, dst);
        axpy_kernel<<<gND, T>>>(dst, alpha, k);
        float4* tmp = src; src = dst; dst = tmp;
    }

    dot_kernel<<<gE16, T>>>(res);
}

// round 5
// speedup vs baseline: 2.8526x; 2.8526x over previous
#include <cuda_runtime.h>

#define NN 100000
#define EE 1200000
#define DD 64
#define DV (DD/4)        // 16 float4 per node row
#define SBS 1024
#define NBLK ((NN + SBS - 1) / SBS)   // 98

// ---- scratch (static device globals; no allocation at runtime) ----
__device__ int    g_is64;
__device__ int    g_cnt [NN];
__device__ int    g_off [NN + 1];
__device__ int    g_cur [NN];
__device__ int    g_bsum[NBLK];
__device__ float  g_dinv[NN];
__device__ int    g_row [EE];
__device__ int    g_col [EE];
__device__ int    g_csrc[EE];          // CSR: source ids grouped by target
__device__ float4 g_xA  [NN * DV];     // prescaled xs ping
__device__ float4 g_xB  [NN * DV];     // prescaled xs pong
__device__ float4 g_out [NN * DV];

// ---- kernels ----

// Detect int64 vs int32 edge_index: if int64 with ids < 2^31, odd words are 0.
__global__ void detect_kernel(const int* __restrict__ ei32) {
    int s = 0;
    #pragma unroll 8
    for (int i = 0; i < 512; ++i) s |= ei32[2 * i + 1];
    g_is64 = (s == 0) ? 1 : 0;
}

__global__ void zero_cnt_kernel() {
    int n = blockIdx.x * blockDim.x + threadIdx.x;
    if (n < NN) g_cnt[n] = 0;
}

// decode edge_index -> row/col, histogram in-degree of col
__global__ void prep_edges_kernel(const void* __restrict__ ei) {
    int e = blockIdx.x * blockDim.x + threadIdx.x;
    if (e < EE) {
        int r, c;
        if (g_is64) {
            const long long* p = (const long long*)ei;
            r = (int)p[e];
            c = (int)p[EE + e];
        } else {
            const int* p = (const int*)ei;
            r = p[e];
            c = p[EE + e];
        }
        if ((unsigned)r >= NN) r = 0;
        if ((unsigned)c >= NN) c = 0;
        g_row[e] = r;
        g_col[e] = c;
        atomicAdd(&g_cnt[c], 1);
    }
}

__global__ void dinv_kernel() {
    int n = blockIdx.x * blockDim.x + threadIdx.x;
    if (n < NN) {
        int d = g_cnt[n];
        g_dinv[n] = (d > 0) ? rsqrtf((float)d) : 0.0f;
    }
}

// ---- exclusive prefix sum of g_cnt into g_off (3 kernels) ----
__global__ void scan1_kernel() {
    __shared__ int sh[SBS];
    int i = blockIdx.x * SBS + threadIdx.x;
    int v = (i < NN) ? g_cnt[i] : 0;
    sh[threadIdx.x] = v;
    __syncthreads();
    for (int d = 1; d < SBS; d <<= 1) {
        int t = (threadIdx.x >= d) ? sh[threadIdx.x - d] : 0;
        __syncthreads();
        sh[threadIdx.x] += t;
        __syncthreads();
    }
    if (i < NN) g_off[i] = sh[threadIdx.x] - v;           // block-local exclusive
    if (threadIdx.x == SBS - 1) g_bsum[blockIdx.x] = sh[SBS - 1];
}

__global__ void scan2_kernel() {      // 1 block, 128 threads >= NBLK
    __shared__ int sh[128];
    int t = threadIdx.x;
    int v = (t < NBLK) ? g_bsum[t] : 0;
    sh[t] = v;
    __syncthreads();
    for (int d = 1; d < 128; d <<= 1) {
        int tmp = (t >= d) ? sh[t - d] : 0;
        __syncthreads();
        sh[t] += tmp;
        __syncthreads();
    }
    if (t < NBLK) g_bsum[t] = sh[t] - v;                  // exclusive block offsets
}

__global__ void scan3_kernel() {
    int i = blockIdx.x * SBS + threadIdx.x;
    if (i < NN) {
        int o = g_off[i] + g_bsum[blockIdx.x];
        g_off[i] = o;
        g_cur[i] = o;
    }
    if (i == 0) g_off[NN] = EE;
}

__global__ void fill_csr_kernel() {
    int e = blockIdx.x * blockDim.x + threadIdx.x;
    if (e < EE) {
        int pos = atomicAdd(&g_cur[g_col[e]], 1);
        g_csrc[pos] = g_row[e];
    }
}

// out = alpha[0] * w ; xs = dinv * w (prescaled for pull hops)
__global__ void init_kernel(const float4* __restrict__ w,
                            const float* __restrict__ alpha) {
    int i = blockIdx.x * blockDim.x + threadIdx.x;
    if (i < NN * DV) {
        float a  = alpha[0];
        float di = g_dinv[i >> 4];
        float4 v = w[i];
        g_xA[i]  = make_float4(di * v.x, di * v.y, di * v.z, di * v.w);
        g_out[i] = make_float4(a * v.x, a * v.y, a * v.z, a * v.w);
    }
}

// Pull hop, fully fused: per node i (16 lanes, one float4 column each)
//   acc = sum_{j in N_in(i)} xs[src_j]
//   x   = dinv[i] * acc
//   out[i] += alpha[k] * x
//   xs_dst[i] = dinv[i] * x        (prescale for next hop)
__global__ void hop_kernel(const float4* __restrict__ xs,
                           float4* __restrict__ xs_dst,
                           const float* __restrict__ alpha, int k,
                           int write_next) {
    int idx = blockIdx.x * blockDim.x + threadIdx.x;     // < NN*16
    if (idx >= NN * DV) return;
    int node = idx >> 4;
    int c    = idx & 15;
    int s    = g_off[node];
    int e    = g_off[node + 1];

    float4 acc = make_float4(0.f, 0.f, 0.f, 0.f);
    // unroll-by-2 for MLP
    for (; s + 1 < e; s += 2) {
        int r0 = g_csrc[s];
        int r1 = g_csrc[s + 1];
        float4 v0 = xs[r0 * DV + c];
        float4 v1 = xs[r1 * DV + c];
        acc.x += v0.x + v1.x; acc.y += v0.y + v1.y;
        acc.z += v0.z + v1.z; acc.w += v0.w + v1.w;
    }
    if (s < e) {
        float4 v = xs[g_csrc[s] * DV + c];
        acc.x += v.x; acc.y += v.y; acc.z += v.z; acc.w += v.w;
    }

    float di = g_dinv[node];
    float a  = alpha[k];
    float4 x = make_float4(di * acc.x, di * acc.y, di * acc.z, di * acc.w);
    float4 o = g_out[idx];
    o.x += a * x.x; o.y += a * x.y; o.z += a * x.z; o.w += a * x.w;
    g_out[idx] = o;
    if (write_next)
        xs_dst[idx] = make_float4(di * x.x, di * x.y, di * x.z, di * x.w);
}

// per-edge dot(out[row], out[col]) with 16 lanes per edge
__global__ void dot_kernel(float* __restrict__ res) {
    int t = blockIdx.x * blockDim.x + threadIdx.x;       // < EE*16 exactly
    int e = t >> 4;
    int c = t & 15;
    float4 a = g_out[g_row[e] * DV + c];
    float4 b = g_out[g_col[e] * DV + c];
    float s = a.x * b.x + a.y * b.y + a.z * b.z + a.w * b.w;
    s += __shfl_down_sync(0xffffffffu, s, 8);
    s += __shfl_down_sync(0xffffffffu, s, 4);
    s += __shfl_down_sync(0xffffffffu, s, 2);
    s += __shfl_down_sync(0xffffffffu, s, 1);
    if (c == 0) res[e] = s;
}

// ---- launch ----
extern "C" void kernel_launch(void* const* d_in, const int* in_sizes, int n_in,
                              void* d_out, int out_size) {
    const void*  ei    = nullptr;
    const float* w     = nullptr;
    const float* alpha = nullptr;
    for (int i = 0; i < n_in; ++i) {
        if (in_sizes[i] == 2 * EE)       ei    = d_in[i];
        else if (in_sizes[i] == NN * DD) w     = (const float*)d_in[i];
        else if (in_sizes[i] == 4)       alpha = (const float*)d_in[i];
    }
    float* res = (float*)d_out;

    void *p_xA, *p_xB;
    cudaGetSymbolAddress(&p_xA, g_xA);
    cudaGetSymbolAddress(&p_xB, g_xB);

    const int T = 256;
    const int gE   = (EE + T - 1) / T;
    const int gN   = (NN + T - 1) / T;
    const int gND  = (NN * DV + T - 1) / T;
    const int gE16 = (EE * 16) / T;

    detect_kernel<<<1, 1>>>((const int*)ei);
    zero_cnt_kernel<<<gN, T>>>();
    prep_edges_kernel<<<gE, T>>>(ei);
    dinv_kernel<<<gN, T>>>();
    scan1_kernel<<<NBLK, SBS>>>();
    scan2_kernel<<<1, 128>>>();
    scan3_kernel<<<NBLK, SBS>>>();
    fill_csr_kernel<<<gE, T>>>();
    init_kernel<<<gND, T>>>((const float4*)w, alpha);

    float4* src = (float4*)p_xA;
    float4* dst = (float4*)p_xB;
    for (int k = 1; k <= 3; ++k) {
        hop_kernel<<<gND, T>>>(src, dst, alpha, k, (k < 3) ? 1 : 0);
        float4* tmp = src; src = dst; dst = tmp;
    }

    dot_kernel<<<gE16, T>>>(res);
}

// round 6
// speedup vs baseline: 3.1818x; 1.1154x over previous
#include <cuda_runtime.h>

#define NN 100000
#define EE 1200000
#define DD 64
#define DV (DD/4)        // 16 float4 per node row
#define SBS 1024
#define NBLK ((NN + SBS - 1) / SBS)   // 98

// ---- scratch (static device globals; no allocation at runtime) ----
__device__ int    g_is64;
__device__ int    g_cnt [NN];
__device__ int    g_off [NN + 1];
__device__ int    g_cur [NN];
__device__ int    g_bsum[NBLK];
__device__ float  g_dinv[NN];
__device__ int    g_row [EE];
__device__ int    g_col [EE];
__device__ int    g_csrc[EE];          // CSR: source ids grouped by target
__device__ float4 g_xA  [NN * DV];     // prescaled xs ping
__device__ float4 g_xB  [NN * DV];     // prescaled xs pong
__device__ float4 g_out [NN * DV];

// ---- kernels ----

// Detect int64 vs int32 edge_index: int64 ids < 2^31 -> odd words all zero.
__global__ void detect_kernel(const int* __restrict__ ei32) {
    int v = ei32[2 * threadIdx.x + 1];
    int any = __syncthreads_or(v != 0);
    if (threadIdx.x == 0) g_is64 = any ? 0 : 1;
}

__global__ void zero_cnt_kernel() {
    int n = blockIdx.x * blockDim.x + threadIdx.x;
    if (n < NN) g_cnt[n] = 0;
}

// decode edge_index -> row/col, histogram in-degree of col
__global__ void prep_edges_kernel(const void* __restrict__ ei) {
    int e = blockIdx.x * blockDim.x + threadIdx.x;
    if (e < EE) {
        int r, c;
        if (g_is64) {
            const long long* p = (const long long*)ei;
            r = (int)p[e];
            c = (int)p[EE + e];
        } else {
            const int* p = (const int*)ei;
            r = p[e];
            c = p[EE + e];
        }
        if ((unsigned)r >= NN) r = 0;
        if ((unsigned)c >= NN) c = 0;
        g_row[e] = r;
        g_col[e] = c;
        atomicAdd(&g_cnt[c], 1);
    }
}

// ---- exclusive prefix sum of g_cnt into g_off (3 kernels) ----
__global__ void scan1_kernel() {
    __shared__ int sh[SBS];
    int i = blockIdx.x * SBS + threadIdx.x;
    int v = (i < NN) ? g_cnt[i] : 0;
    sh[threadIdx.x] = v;
    __syncthreads();
    for (int d = 1; d < SBS; d <<= 1) {
        int t = (threadIdx.x >= d) ? sh[threadIdx.x - d] : 0;
        __syncthreads();
        sh[threadIdx.x] += t;
        __syncthreads();
    }
    if (i < NN) g_off[i] = sh[threadIdx.x] - v;           // block-local exclusive
    if (threadIdx.x == SBS - 1) g_bsum[blockIdx.x] = sh[SBS - 1];
}

__global__ void scan2_kernel() {      // 1 block, 128 threads >= NBLK
    __shared__ int sh[128];
    int t = threadIdx.x;
    int v = (t < NBLK) ? g_bsum[t] : 0;
    sh[t] = v;
    __syncthreads();
    for (int d = 1; d < 128; d <<= 1) {
        int tmp = (t >= d) ? sh[t - d] : 0;
        __syncthreads();
        sh[t] += tmp;
        __syncthreads();
    }
    if (t < NBLK) g_bsum[t] = sh[t] - v;                  // exclusive block offsets
}

// add-back + dinv fused
__global__ void scan3_kernel() {
    int i = blockIdx.x * SBS + threadIdx.x;
    if (i < NN) {
        int o = g_off[i] + g_bsum[blockIdx.x];
        g_off[i] = o;
        g_cur[i] = o;
        int d = g_cnt[i];
        g_dinv[i] = (d > 0) ? rsqrtf((float)d) : 0.0f;
    }
    if (i == 0) g_off[NN] = EE;
}

__global__ void fill_csr_kernel() {
    int e = blockIdx.x * blockDim.x + threadIdx.x;
    if (e < EE) {
        int pos = atomicAdd(&g_cur[g_col[e]], 1);
        g_csrc[pos] = g_row[e];
    }
}

// Hop 1, fused with init: per (node, float4-column)
//   acc = sum_j dinv[src_j] * w[src_j]
//   x   = dinv[i] * acc
//   out[i]   = alpha[0]*w[i] + alpha[1]*x
//   xs_dst[i]= dinv[i] * x
__global__ void hop_first_kernel(const float4* __restrict__ w,
                                 float4* __restrict__ xs_dst,
                                 const float* __restrict__ alpha) {
    int idx = blockIdx.x * blockDim.x + threadIdx.x;
    if (idx >= NN * DV) return;
    int node = idx >> 4;
    int c    = idx & 15;
    int s    = g_off[node];
    int e    = g_off[node + 1];

    float4 acc = make_float4(0.f, 0.f, 0.f, 0.f);
    for (; s + 1 < e; s += 2) {
        int r0 = g_csrc[s];
        int r1 = g_csrc[s + 1];
        float d0 = g_dinv[r0];
        float d1 = g_dinv[r1];
        float4 v0 = w[r0 * DV + c];
        float4 v1 = w[r1 * DV + c];
        acc.x += d0 * v0.x + d1 * v1.x;
        acc.y += d0 * v0.y + d1 * v1.y;
        acc.z += d0 * v0.z + d1 * v1.z;
        acc.w += d0 * v0.w + d1 * v1.w;
    }
    if (s < e) {
        int r0 = g_csrc[s];
        float d0 = g_dinv[r0];
        float4 v0 = w[r0 * DV + c];
        acc.x += d0 * v0.x; acc.y += d0 * v0.y;
        acc.z += d0 * v0.z; acc.w += d0 * v0.w;
    }

    float di = g_dinv[node];
    float a0 = alpha[0];
    float a1 = alpha[1];
    float4 x = make_float4(di * acc.x, di * acc.y, di * acc.z, di * acc.w);
    float4 wv = w[idx];
    g_out[idx] = make_float4(a0 * wv.x + a1 * x.x,
                             a0 * wv.y + a1 * x.y,
                             a0 * wv.z + a1 * x.z,
                             a0 * wv.w + a1 * x.w);
    xs_dst[idx] = make_float4(di * x.x, di * x.y, di * x.z, di * x.w);
}

// Hops 2..K: pull from prescaled xs
__global__ void hop_kernel(const float4* __restrict__ xs,
                           float4* __restrict__ xs_dst,
                           const float* __restrict__ alpha, int k,
                           int write_next) {
    int idx = blockIdx.x * blockDim.x + threadIdx.x;
    if (idx >= NN * DV) return;
    int node = idx >> 4;
    int c    = idx & 15;
    int s    = g_off[node];
    int e    = g_off[node + 1];

    float4 acc = make_float4(0.f, 0.f, 0.f, 0.f);
    for (; s + 1 < e; s += 2) {
        int r0 = g_csrc[s];
        int r1 = g_csrc[s + 1];
        float4 v0 = xs[r0 * DV + c];
        float4 v1 = xs[r1 * DV + c];
        acc.x += v0.x + v1.x; acc.y += v0.y + v1.y;
        acc.z += v0.z + v1.z; acc.w += v0.w + v1.w;
    }
    if (s < e) {
        float4 v = xs[g_csrc[s] * DV + c];
        acc.x += v.x; acc.y += v.y; acc.z += v.z; acc.w += v.w;
    }

    float di = g_dinv[node];
    float a  = alpha[k];
    float4 x = make_float4(di * acc.x, di * acc.y, di * acc.z, di * acc.w);
    float4 o = g_out[idx];
    o.x += a * x.x; o.y += a * x.y; o.z += a * x.z; o.w += a * x.w;
    g_out[idx] = o;
    if (write_next)
        xs_dst[idx] = make_float4(di * x.x, di * x.y, di * x.z, di * x.w);
}

// per-edge dot(out[row], out[col]) with 16 lanes per edge
__global__ void dot_kernel(float* __restrict__ res) {
    int t = blockIdx.x * blockDim.x + threadIdx.x;       // < EE*16 exactly
    int e = t >> 4;
    int c = t & 15;
    float4 a = g_out[g_row[e] * DV + c];
    float4 b = g_out[g_col[e] * DV + c];
    float s = a.x * b.x + a.y * b.y + a.z * b.z + a.w * b.w;
    s += __shfl_down_sync(0xffffffffu, s, 8);
    s += __shfl_down_sync(0xffffffffu, s, 4);
    s += __shfl_down_sync(0xffffffffu, s, 2);
    s += __shfl_down_sync(0xffffffffu, s, 1);
    if (c == 0) res[e] = s;
}

// ---- launch ----
extern "C" void kernel_launch(void* const* d_in, const int* in_sizes, int n_in,
                              void* d_out, int out_size) {
    const void*  ei    = nullptr;
    const float* w     = nullptr;
    const float* alpha = nullptr;
    for (int i = 0; i < n_in; ++i) {
        if (in_sizes[i] == 2 * EE)       ei    = d_in[i];
        else if (in_sizes[i] == NN * DD) w     = (const float*)d_in[i];
        else if (in_sizes[i] == 4)       alpha = (const float*)d_in[i];
    }
    float* res = (float*)d_out;

    void *p_xA, *p_xB;
    cudaGetSymbolAddress(&p_xA, g_xA);
    cudaGetSymbolAddress(&p_xB, g_xB);

    const int T = 256;
    const int gE   = (EE + T - 1) / T;
    const int gN   = (NN + T - 1) / T;
    const int gND  = (NN * DV + T - 1) / T;
    const int gE16 = (EE * 16) / T;

    detect_kernel<<<1, 512>>>((const int*)ei);
    zero_cnt_kernel<<<gN, T>>>();
    prep_edges_kernel<<<gE, T>>>(ei);
    scan1_kernel<<<NBLK, SBS>>>();
    scan2_kernel<<<1, 128>>>();
    scan3_kernel<<<NBLK, SBS>>>();
    fill_csr_kernel<<<gE, T>>>();

    float4* bufA = (float4*)p_xA;
    float4* bufB = (float4*)p_xB;

    hop_first_kernel<<<gND, T>>>((const float4*)w, bufA, alpha);      // k=1
    hop_kernel<<<gND, T>>>(bufA, bufB, alpha, 2, 1);                  // k=2
    hop_kernel<<<gND, T>>>(bufB, bufA, alpha, 3, 0);                  // k=3

    dot_kernel<<<gE16, T>>>(res);
}

// round 7
// speedup vs baseline: 3.5643x; 1.1202x over previous
#include <cuda_runtime.h>

#define NN 100000
#define EE 1200000
#define DD 64
#define DV (DD/4)        // 16 float4 per node row
#define SBS 1024
#define NBLK ((NN + SBS - 1) / SBS)   // 98

// ---- scratch (static device globals; no allocation at runtime) ----
__device__ int    g_is64;
__device__ int    g_cnt [NN];
__device__ int    g_off [NN + 1];
__device__ int    g_cur [NN];
__device__ int    g_bsum[NBLK];
__device__ float  g_dinv[NN];
__device__ int    g_row [EE];
__device__ int    g_col [EE];
__device__ int    g_csrc[EE];          // CSR: source ids grouped by target
__device__ int    g_eid [EE];          // CSR: original edge id
__device__ float4 g_xA  [NN * DV];
__device__ float4 g_xB  [NN * DV];
__device__ float4 g_out [NN * DV];

// ---- kernels ----

// zero histogram; block 0 additionally detects int64 vs int32 edge_index
__global__ void prep0_kernel(const int* __restrict__ ei32) {
    int n = blockIdx.x * blockDim.x + threadIdx.x;
    if (n < NN) g_cnt[n] = 0;
    if (blockIdx.x == 0) {
        int v = ei32[2 * threadIdx.x + 1];
        int any = __syncthreads_or(v != 0);
        if (threadIdx.x == 0) g_is64 = any ? 0 : 1;
    }
}

// decode edge_index -> row/col, histogram in-degree of col
__global__ void prep_edges_kernel(const void* __restrict__ ei) {
    int e = blockIdx.x * blockDim.x + threadIdx.x;
    if (e < EE) {
        int r, c;
        if (g_is64) {
            const long long* p = (const long long*)ei;
            r = (int)p[e];
            c = (int)p[EE + e];
        } else {
            const int* p = (const int*)ei;
            r = p[e];
            c = p[EE + e];
        }
        if ((unsigned)r >= NN) r = 0;
        if ((unsigned)c >= NN) c = 0;
        g_row[e] = r;
        g_col[e] = c;
        atomicAdd(&g_cnt[c], 1);
    }
}

// block-local exclusive scan of g_cnt; block sums to g_bsum
__global__ void scan1_kernel() {
    __shared__ int sh[SBS];
    int i = blockIdx.x * SBS + threadIdx.x;
    int v = (i < NN) ? g_cnt[i] : 0;
    sh[threadIdx.x] = v;
    __syncthreads();
    for (int d = 1; d < SBS; d <<= 1) {
        int t = (threadIdx.x >= d) ? sh[threadIdx.x - d] : 0;
        __syncthreads();
        sh[threadIdx.x] += t;
        __syncthreads();
    }
    if (i < NN) g_off[i] = sh[threadIdx.x] - v;
    if (threadIdx.x == SBS - 1) g_bsum[blockIdx.x] = sh[SBS - 1];
}

// add-back (each block re-scans the 98 block sums) + dinv + cursor init
__global__ void scan2_kernel() {
    __shared__ int bs[128];
    if (threadIdx.x < 128)
        bs[threadIdx.x] = (threadIdx.x < NBLK) ? g_bsum[threadIdx.x] : 0;
    __syncthreads();
    for (int d = 1; d < 128; d <<= 1) {
        int t = (threadIdx.x >= d && threadIdx.x < 128) ? bs[threadIdx.x - d] : 0;
        __syncthreads();
        if (threadIdx.x < 128) bs[threadIdx.x] += t;
        __syncthreads();
    }
    int add = (blockIdx.x == 0) ? 0 : bs[blockIdx.x - 1];   // exclusive
    int i = blockIdx.x * SBS + threadIdx.x;
    if (i < NN) {
        int o = g_off[i] + add;
        g_off[i] = o;
        g_cur[i] = o;
        int d = g_cnt[i];
        g_dinv[i] = (d > 0) ? rsqrtf((float)d) : 0.0f;
    }
    if (i == 0) g_off[NN] = EE;
}

__global__ void fill_csr_kernel() {
    int e = blockIdx.x * blockDim.x + threadIdx.x;
    if (e < EE) {
        int pos = atomicAdd(&g_cur[g_col[e]], 1);
        g_csrc[pos] = g_row[e];
        g_eid [pos] = e;
    }
}

// Hop 1 fused with init:
//   x = dinv[i] * sum_j dinv[src]*w[src];  out = a0*w + a1*x;  xs = dinv[i]*x
__global__ void hop_first_kernel(const float4* __restrict__ w,
                                 float4* __restrict__ xs_dst,
                                 const float* __restrict__ alpha) {
    int idx = blockIdx.x * blockDim.x + threadIdx.x;
    if (idx >= NN * DV) return;
    int node = idx >> 4;
    int c    = idx & 15;
    int s    = g_off[node];
    int e    = g_off[node + 1];

    float4 acc = make_float4(0.f, 0.f, 0.f, 0.f);
    for (; s + 3 < e; s += 4) {
        int r0 = g_csrc[s],     r1 = g_csrc[s + 1];
        int r2 = g_csrc[s + 2], r3 = g_csrc[s + 3];
        float d0 = g_dinv[r0], d1 = g_dinv[r1], d2 = g_dinv[r2], d3 = g_dinv[r3];
        float4 v0 = w[r0 * DV + c], v1 = w[r1 * DV + c];
        float4 v2 = w[r2 * DV + c], v3 = w[r3 * DV + c];
        acc.x += d0*v0.x + d1*v1.x + d2*v2.x + d3*v3.x;
        acc.y += d0*v0.y + d1*v1.y + d2*v2.y + d3*v3.y;
        acc.z += d0*v0.z + d1*v1.z + d2*v2.z + d3*v3.z;
        acc.w += d0*v0.w + d1*v1.w + d2*v2.w + d3*v3.w;
    }
    for (; s < e; ++s) {
        int r0 = g_csrc[s];
        float d0 = g_dinv[r0];
        float4 v0 = w[r0 * DV + c];
        acc.x += d0*v0.x; acc.y += d0*v0.y; acc.z += d0*v0.z; acc.w += d0*v0.w;
    }

    float di = g_dinv[node];
    float a0 = alpha[0];
    float a1 = alpha[1];
    float4 x = make_float4(di*acc.x, di*acc.y, di*acc.z, di*acc.w);
    float4 wv = w[idx];
    g_out[idx] = make_float4(a0*wv.x + a1*x.x, a0*wv.y + a1*x.y,
                             a0*wv.z + a1*x.z, a0*wv.w + a1*x.w);
    xs_dst[idx] = make_float4(di*x.x, di*x.y, di*x.z, di*x.w);
}

// Hops 2..K: pull from prescaled xs
__global__ void hop_kernel(const float4* __restrict__ xs,
                           float4* __restrict__ xs_dst,
                           const float* __restrict__ alpha, int k,
                           int write_next) {
    int idx = blockIdx.x * blockDim.x + threadIdx.x;
    if (idx >= NN * DV) return;
    int node = idx >> 4;
    int c    = idx & 15;
    int s    = g_off[node];
    int e    = g_off[node + 1];

    float4 acc = make_float4(0.f, 0.f, 0.f, 0.f);
    for (; s + 3 < e; s += 4) {
        int r0 = g_csrc[s],     r1 = g_csrc[s + 1];
        int r2 = g_csrc[s + 2], r3 = g_csrc[s + 3];
        float4 v0 = xs[r0 * DV + c], v1 = xs[r1 * DV + c];
        float4 v2 = xs[r2 * DV + c], v3 = xs[r3 * DV + c];
        acc.x += (v0.x + v1.x) + (v2.x + v3.x);
        acc.y += (v0.y + v1.y) + (v2.y + v3.y);
        acc.z += (v0.z + v1.z) + (v2.z + v3.z);
        acc.w += (v0.w + v1.w) + (v2.w + v3.w);
    }
    for (; s < e; ++s) {
        float4 v = xs[g_csrc[s] * DV + c];
        acc.x += v.x; acc.y += v.y; acc.z += v.z; acc.w += v.w;
    }

    float di = g_dinv[node];
    float a  = alpha[k];
    float4 x = make_float4(di*acc.x, di*acc.y, di*acc.z, di*acc.w);
    float4 o = g_out[idx];
    o.x += a*x.x; o.y += a*x.y; o.z += a*x.z; o.w += a*x.w;
    g_out[idx] = o;
    if (write_next)
        xs_dst[idx] = make_float4(di*x.x, di*x.y, di*x.z, di*x.w);
}

// CSR-ordered link scores: 16 lanes per node hold out[node] in registers,
// loop over in-edges gathering only out[src]; scatter to res[eid].
__global__ void dot_csr_kernel(float* __restrict__ res) {
    int idx = blockIdx.x * blockDim.x + threadIdx.x;     // < NN*16
    if (idx >= NN * DV) return;
    int node = idx >> 4;
    int c    = idx & 15;
    int lane = threadIdx.x & 31;
    unsigned mask = 0xFFFFu << (lane & 16);              // this half-warp

    float4 oi = g_out[node * DV + c];
    int s = g_off[node];
    int e = g_off[node + 1];
    for (; s < e; ++s) {
        int r   = g_csrc[s];
        int eid = g_eid[s];
        float4 orow = g_out[r * DV + c];
        float p = oi.x*orow.x + oi.y*orow.y + oi.z*orow.z + oi.w*orow.w;
        p += __shfl_down_sync(mask, p, 8, 16);
        p += __shfl_down_sync(mask, p, 4, 16);
        p += __shfl_down_sync(mask, p, 2, 16);
        p += __shfl_down_sync(mask, p, 1, 16);
        if (c == 0) res[eid] = p;
    }
}

// ---- launch ----
extern "C" void kernel_launch(void* const* d_in, const int* in_sizes, int n_in,
                              void* d_out, int out_size) {
    const void*  ei    = nullptr;
    const float* w     = nullptr;
    const float* alpha = nullptr;
    for (int i = 0; i < n_in; ++i) {
        if (in_sizes[i] == 2 * EE)       ei    = d_in[i];
        else if (in_sizes[i] == NN * DD) w     = (const float*)d_in[i];
        else if (in_sizes[i] == 4)       alpha = (const float*)d_in[i];
    }
    float* res = (float*)d_out;

    void *p_xA, *p_xB;
    cudaGetSymbolAddress(&p_xA, g_xA);
    cudaGetSymbolAddress(&p_xB, g_xB);

    const int T = 256;
    const int gE  = (EE + T - 1) / T;
    const int gN  = (NN + T - 1) / T;
    const int gND = (NN * DV + T - 1) / T;

    prep0_kernel<<<gN, T>>>((const int*)ei);
    prep_edges_kernel<<<gE, T>>>(ei);
    scan1_kernel<<<NBLK, SBS>>>();
    scan2_kernel<<<NBLK, SBS>>>();
    fill_csr_kernel<<<gE, T>>>();

    float4* bufA = (float4*)p_xA;
    float4* bufB = (float4*)p_xB;

    hop_first_kernel<<<gND, T>>>((const float4*)w, bufA, alpha);   // k=1
    hop_kernel<<<gND, T>>>(bufA, bufB, alpha, 2, 1);               // k=2
    hop_kernel<<<gND, T>>>(bufB, bufA, alpha, 3, 0);               // k=3

    dot_csr_kernel<<<gND, T>>>(res);
}

// round 8
// speedup vs baseline: 3.9840x; 1.1178x over previous
#include <cuda_runtime.h>
#include <cuda_fp16.h>

#define NN 100000
#define EE 1200000
#define DD 64
#define DV (DD/4)        // 16 float4 per node row (f32)
#define HV 16            // 16 uint2 per node row (fp16: 4 halves each)
#define SBS 1024
#define NBLK ((NN + SBS - 1) / SBS)   // 98

// ---- scratch (static device globals; no allocation at runtime) ----
__device__ int    g_is64;
__device__ int    g_cnt [NN];
__device__ int    g_off [NN + 1];
__device__ int    g_cur [NN];
__device__ int    g_bsum[NBLK];
__device__ float  g_dinv[NN];
__device__ int    g_row [EE];
__device__ int    g_col [EE];
__device__ int    g_csrc[EE];          // CSR: source ids grouped by target
__device__ int    g_eid [EE];          // CSR: original edge id
__device__ uint2  g_hA  [NN * HV];     // fp16 xs ping
__device__ uint2  g_hB  [NN * HV];     // fp16 xs pong
__device__ uint2  g_hOut[NN * HV];     // fp16 shadow of out (dot gathers)
__device__ float4 g_out [NN * DV];     // f32 out

// ---- helpers ----
__device__ __forceinline__ uint2 pack_half4(float x, float y, float z, float w) {
    __half2 a = __floats2half2_rn(x, y);
    __half2 b = __floats2half2_rn(z, w);
    uint2 u;
    u.x = *(unsigned int*)&a;
    u.y = *(unsigned int*)&b;
    return u;
}
__device__ __forceinline__ float4 unpack_half4(uint2 u) {
    __half2 a = *(__half2*)&u.x;
    __half2 b = *(__half2*)&u.y;
    float2 f0 = __half22float2(a);
    float2 f1 = __half22float2(b);
    return make_float4(f0.x, f0.y, f1.x, f1.y);
}

// ---- kernels ----

// zero histogram; block 0 additionally detects int64 vs int32 edge_index
__global__ void prep0_kernel(const int* __restrict__ ei32) {
    int n = blockIdx.x * blockDim.x + threadIdx.x;
    if (n < NN) g_cnt[n] = 0;
    if (blockIdx.x == 0) {
        int v = ei32[2 * threadIdx.x + 1];
        int any = __syncthreads_or(v != 0);
        if (threadIdx.x == 0) g_is64 = any ? 0 : 1;
    }
}

__global__ void prep_edges_kernel(const void* __restrict__ ei) {
    int e = blockIdx.x * blockDim.x + threadIdx.x;
    if (e < EE) {
        int r, c;
        if (g_is64) {
            const long long* p = (const long long*)ei;
            r = (int)p[e];
            c = (int)p[EE + e];
        } else {
            const int* p = (const int*)ei;
            r = p[e];
            c = p[EE + e];
        }
        if ((unsigned)r >= NN) r = 0;
        if ((unsigned)c >= NN) c = 0;
        g_row[e] = r;
        g_col[e] = c;
        atomicAdd(&g_cnt[c], 1);
    }
}

// warp-shuffle block scan: block-local exclusive offsets + block sums
__global__ void scan1_kernel() {
    __shared__ int wsum[32];
    int t    = threadIdx.x;
    int lane = t & 31;
    int warp = t >> 5;
    int i = blockIdx.x * SBS + t;
    int v = (i < NN) ? g_cnt[i] : 0;
    int x = v;
    #pragma unroll
    for (int d = 1; d < 32; d <<= 1) {
        int y = __shfl_up_sync(0xFFFFFFFFu, x, d);
        if (lane >= d) x += y;
    }
    if (lane == 31) wsum[warp] = x;
    __syncthreads();
    if (warp == 0) {
        int s = wsum[lane];
        #pragma unroll
        for (int d = 1; d < 32; d <<= 1) {
            int y = __shfl_up_sync(0xFFFFFFFFu, s, d);
            if (lane >= d) s += y;
        }
        wsum[lane] = s;
    }
    __syncthreads();
    int incl = x + ((warp > 0) ? wsum[warp - 1] : 0);
    if (i < NN) g_off[i] = incl - v;
    if (t == SBS - 1) g_bsum[blockIdx.x] = incl;
}

// add-back (warp 0 re-scans the 98 block sums) + dinv + cursor init
__global__ void scan2_kernel() {
    __shared__ int bs[128];
    int t = threadIdx.x;
    if (t < 128) bs[t] = (t < NBLK) ? g_bsum[t] : 0;
    __syncthreads();
    if (t < 32) {
        int carry = 0;
        #pragma unroll
        for (int ch = 0; ch < 4; ++ch) {
            int x = bs[ch * 32 + t];
            #pragma unroll
            for (int d = 1; d < 32; d <<= 1) {
                int y = __shfl_up_sync(0xFFFFFFFFu, x, d);
                if (t >= d) x += y;
            }
            bs[ch * 32 + t] = x + carry;
            carry = __shfl_sync(0xFFFFFFFFu, x + carry, 31);
        }
    }
    __syncthreads();
    int add = (blockIdx.x == 0) ? 0 : bs[blockIdx.x - 1];
    int i = blockIdx.x * SBS + t;
    if (i < NN) {
        int o = g_off[i] + add;
        g_off[i] = o;
        g_cur[i] = o;
        int d = g_cnt[i];
        g_dinv[i] = (d > 0) ? rsqrtf((float)d) : 0.0f;
    }
    if (i == 0) g_off[NN] = EE;
}

__global__ void fill_csr_kernel() {
    int e = blockIdx.x * blockDim.x + threadIdx.x;
    if (e < EE) {
        int pos = atomicAdd(&g_cur[g_col[e]], 1);
        g_csrc[pos] = g_row[e];
        g_eid [pos] = e;
    }
}

// Hop 1 fused with init: gathers f32 w, writes f32 out and fp16 xs
__global__ void hop_first_kernel(const float4* __restrict__ w,
                                 const float* __restrict__ alpha) {
    int idx = blockIdx.x * blockDim.x + threadIdx.x;
    if (idx >= NN * DV) return;
    int node = idx >> 4;
    int c    = idx & 15;
    int s    = g_off[node];
    int e    = g_off[node + 1];

    float4 acc = make_float4(0.f, 0.f, 0.f, 0.f);
    for (; s + 3 < e; s += 4) {
        int r0 = g_csrc[s],     r1 = g_csrc[s + 1];
        int r2 = g_csrc[s + 2], r3 = g_csrc[s + 3];
        float d0 = g_dinv[r0], d1 = g_dinv[r1], d2 = g_dinv[r2], d3 = g_dinv[r3];
        float4 v0 = w[r0 * DV + c], v1 = w[r1 * DV + c];
        float4 v2 = w[r2 * DV + c], v3 = w[r3 * DV + c];
        acc.x += d0*v0.x + d1*v1.x + d2*v2.x + d3*v3.x;
        acc.y += d0*v0.y + d1*v1.y + d2*v2.y + d3*v3.y;
        acc.z += d0*v0.z + d1*v1.z + d2*v2.z + d3*v3.z;
        acc.w += d0*v0.w + d1*v1.w + d2*v2.w + d3*v3.w;
    }
    for (; s < e; ++s) {
        int r0 = g_csrc[s];
        float d0 = g_dinv[r0];
        float4 v0 = w[r0 * DV + c];
        acc.x += d0*v0.x; acc.y += d0*v0.y; acc.z += d0*v0.z; acc.w += d0*v0.w;
    }

    float di = g_dinv[node];
    float a0 = alpha[0];
    float a1 = alpha[1];
    float4 x = make_float4(di*acc.x, di*acc.y, di*acc.z, di*acc.w);
    float4 wv = w[idx];
    g_out[idx] = make_float4(a0*wv.x + a1*x.x, a0*wv.y + a1*x.y,
                             a0*wv.z + a1*x.z, a0*wv.w + a1*x.w);
    g_hA[idx] = pack_half4(di*x.x, di*x.y, di*x.z, di*x.w);
}

// Hops 2..K: gather fp16 xs, f32 accumulate.
// write_next=1 -> write fp16 xs_dst for next hop
// write_next=0 -> final hop: write fp16 shadow of updated out
__global__ void hop_kernel(const uint2* __restrict__ xs,
                           uint2* __restrict__ xs_dst,
                           const float* __restrict__ alpha, int k,
                           int write_next) {
    int idx = blockIdx.x * blockDim.x + threadIdx.x;
    if (idx >= NN * DV) return;
    int node = idx >> 4;
    int c    = idx & 15;
    int s    = g_off[node];
    int e    = g_off[node + 1];

    float4 acc = make_float4(0.f, 0.f, 0.f, 0.f);
    for (; s + 3 < e; s += 4) {
        int r0 = g_csrc[s],     r1 = g_csrc[s + 1];
        int r2 = g_csrc[s + 2], r3 = g_csrc[s + 3];
        float4 v0 = unpack_half4(xs[r0 * HV + c]);
        float4 v1 = unpack_half4(xs[r1 * HV + c]);
        float4 v2 = unpack_half4(xs[r2 * HV + c]);
        float4 v3 = unpack_half4(xs[r3 * HV + c]);
        acc.x += (v0.x + v1.x) + (v2.x + v3.x);
        acc.y += (v0.y + v1.y) + (v2.y + v3.y);
        acc.z += (v0.z + v1.z) + (v2.z + v3.z);
        acc.w += (v0.w + v1.w) + (v2.w + v3.w);
    }
    for (; s < e; ++s) {
        float4 v = unpack_half4(xs[g_csrc[s] * HV + c]);
        acc.x += v.x; acc.y += v.y; acc.z += v.z; acc.w += v.w;
    }

    float di = g_dinv[node];
    float a  = alpha[k];
    float4 x = make_float4(di*acc.x, di*acc.y, di*acc.z, di*acc.w);
    float4 o = g_out[idx];
    o.x += a*x.x; o.y += a*x.y; o.z += a*x.z; o.w += a*x.w;
    g_out[idx] = o;
    if (write_next)
        xs_dst[idx] = pack_half4(di*x.x, di*x.y, di*x.z, di*x.w);
    else
        g_hOut[idx] = pack_half4(o.x, o.y, o.z, o.w);
}

// CSR-ordered link scores: oi from f32 out (per-node), gather fp16 out shadow.
__global__ void dot_csr_kernel(float* __restrict__ res) {
    int idx = blockIdx.x * blockDim.x + threadIdx.x;     // < NN*16
    if (idx >= NN * DV) return;
    int node = idx >> 4;
    int c    = idx & 15;
    int lane = threadIdx.x & 31;
    unsigned mask = 0xFFFFu << (lane & 16);              // this half-warp

    float4 oi = g_out[node * DV + c];
    int s = g_off[node];
    int e = g_off[node + 1];
    for (; s < e; ++s) {
        int r   = g_csrc[s];
        int eid = g_eid[s];
        float4 orow = unpack_half4(g_hOut[r * HV + c]);
        float p = oi.x*orow.x + oi.y*orow.y + oi.z*orow.z + oi.w*orow.w;
        p += __shfl_down_sync(mask, p, 8, 16);
        p += __shfl_down_sync(mask, p, 4, 16);
        p += __shfl_down_sync(mask, p, 2, 16);
        p += __shfl_down_sync(mask, p, 1, 16);
        if (c == 0) res[eid] = p;
    }
}

// ---- launch ----
extern "C" void kernel_launch(void* const* d_in, const int* in_sizes, int n_in,
                              void* d_out, int out_size) {
    const void*  ei    = nullptr;
    const float* w     = nullptr;
    const float* alpha = nullptr;
    for (int i = 0; i < n_in; ++i) {
        if (in_sizes[i] == 2 * EE)       ei    = d_in[i];
        else if (in_sizes[i] == NN * DD) w     = (const float*)d_in[i];
        else if (in_sizes[i] == 4)       alpha = (const float*)d_in[i];
    }
    float* res = (float*)d_out;

    void *p_hA, *p_hB;
    cudaGetSymbolAddress(&p_hA, g_hA);
    cudaGetSymbolAddress(&p_hB, g_hB);

    const int T = 256;
    const int gE  = (EE + T - 1) / T;
    const int gN  = (NN + T - 1) / T;
    const int gND = (NN * DV + T - 1) / T;

    prep0_kernel<<<gN, T>>>((const int*)ei);
    prep_edges_kernel<<<gE, T>>>(ei);
    scan1_kernel<<<NBLK, SBS>>>();
    scan2_kernel<<<NBLK, SBS>>>();
    fill_csr_kernel<<<gE, T>>>();

    uint2* hA = (uint2*)p_hA;
    uint2* hB = (uint2*)p_hB;

    hop_first_kernel<<<gND, T>>>((const float4*)w, alpha);   // k=1 -> hA
    hop_kernel<<<gND, T>>>(hA, hB, alpha, 2, 1);             // k=2 -> hB
    hop_kernel<<<gND, T>>>(hB, hA, alpha, 3, 0);             // k=3 -> g_hOut

    dot_csr_kernel<<<gND, T>>>(res);
}

// round 9
// speedup vs baseline: 4.1483x; 1.0412x over previous
#include <cuda_runtime.h>
#include <cuda_fp16.h>

#define NN 100000
#define EE 1200000
#define DD 64
#define DV (DD/4)        // 16 float4 per node row (f32)
#define HQ 8             // 8 uint4 per node row (fp16: 8 halves each)
#define SBS 1024
#define NBLK ((NN + SBS - 1) / SBS)   // 98

// ---- scratch (static device globals; no allocation at runtime) ----
__device__ int    g_is64;
__device__ int    g_cnt [NN];
__device__ int    g_off [NN + 1];
__device__ int    g_cur [NN];
__device__ int    g_bsum[NBLK];
__device__ float  g_dinv[NN];
__device__ int    g_row [EE];
__device__ int    g_col [EE];
__device__ int    g_csrc[EE];          // CSR: source ids grouped by target
__device__ int    g_eid [EE];          // CSR: original edge id
__device__ uint4  g_hW  [NN * HQ];     // fp16 prescaled dinv*w
__device__ uint4  g_hA  [NN * HQ];     // fp16 xs ping
__device__ uint4  g_hB  [NN * HQ];     // fp16 xs pong
__device__ uint4  g_hO  [NN * HQ];     // fp16 shadow of out (dot gathers)
__device__ float4 g_out [NN * DV];     // f32 out

// ---- helpers ----
__device__ __forceinline__ unsigned h2u(__half2 h) { return *(unsigned*)&h; }
__device__ __forceinline__ __half2 u2h(unsigned u) { return *(__half2*)&u; }

__device__ __forceinline__ uint4 pack_half8(float4 lo, float4 hi) {
    uint4 u;
    u.x = h2u(__floats2half2_rn(lo.x, lo.y));
    u.y = h2u(__floats2half2_rn(lo.z, lo.w));
    u.z = h2u(__floats2half2_rn(hi.x, hi.y));
    u.w = h2u(__floats2half2_rn(hi.z, hi.w));
    return u;
}
__device__ __forceinline__ void unpack_half8(uint4 u, float4& lo, float4& hi) {
    float2 a = __half22float2(u2h(u.x));
    float2 b = __half22float2(u2h(u.y));
    float2 c = __half22float2(u2h(u.z));
    float2 d = __half22float2(u2h(u.w));
    lo = make_float4(a.x, a.y, b.x, b.y);
    hi = make_float4(c.x, c.y, d.x, d.y);
}

// ---- kernels ----

__global__ void prep0_kernel(const int* __restrict__ ei32) {
    int n = blockIdx.x * blockDim.x + threadIdx.x;
    if (n < NN) g_cnt[n] = 0;
    if (blockIdx.x == 0) {
        int v = ei32[2 * threadIdx.x + 1];
        int any = __syncthreads_or(v != 0);
        if (threadIdx.x == 0) g_is64 = any ? 0 : 1;
    }
}

__global__ void prep_edges_kernel(const void* __restrict__ ei) {
    int e = blockIdx.x * blockDim.x + threadIdx.x;
    if (e < EE) {
        int r, c;
        if (g_is64) {
            const long long* p = (const long long*)ei;
            r = (int)p[e];
            c = (int)p[EE + e];
        } else {
            const int* p = (const int*)ei;
            r = p[e];
            c = p[EE + e];
        }
        if ((unsigned)r >= NN) r = 0;
        if ((unsigned)c >= NN) c = 0;
        g_row[e] = r;
        g_col[e] = c;
        atomicAdd(&g_cnt[c], 1);
    }
}

// warp-shuffle block scan: block-local exclusive offsets + block sums
__global__ void scan1_kernel() {
    __shared__ int wsum[32];
    int t    = threadIdx.x;
    int lane = t & 31;
    int warp = t >> 5;
    int i = blockIdx.x * SBS + t;
    int v = (i < NN) ? g_cnt[i] : 0;
    int x = v;
    #pragma unroll
    for (int d = 1; d < 32; d <<= 1) {
        int y = __shfl_up_sync(0xFFFFFFFFu, x, d);
        if (lane >= d) x += y;
    }
    if (lane == 31) wsum[warp] = x;
    __syncthreads();
    if (warp == 0) {
        int s = wsum[lane];
        #pragma unroll
        for (int d = 1; d < 32; d <<= 1) {
            int y = __shfl_up_sync(0xFFFFFFFFu, s, d);
            if (lane >= d) s += y;
        }
        wsum[lane] = s;
    }
    __syncthreads();
    int incl = x + ((warp > 0) ? wsum[warp - 1] : 0);
    if (i < NN) g_off[i] = incl - v;
    if (t == SBS - 1) g_bsum[blockIdx.x] = incl;
}

// add-back + dinv + cursor init
__global__ void scan2_kernel() {
    __shared__ int bs[128];
    int t = threadIdx.x;
    if (t < 128) bs[t] = (t < NBLK) ? g_bsum[t] : 0;
    __syncthreads();
    if (t < 32) {
        int carry = 0;
        #pragma unroll
        for (int ch = 0; ch < 4; ++ch) {
            int x = bs[ch * 32 + t];
            #pragma unroll
            for (int d = 1; d < 32; d <<= 1) {
                int y = __shfl_up_sync(0xFFFFFFFFu, x, d);
                if (t >= d) x += y;
            }
            bs[ch * 32 + t] = x + carry;
            carry = __shfl_sync(0xFFFFFFFFu, x + carry, 31);
        }
    }
    __syncthreads();
    int add = (blockIdx.x == 0) ? 0 : bs[blockIdx.x - 1];
    int i = blockIdx.x * SBS + t;
    if (i < NN) {
        int o = g_off[i] + add;
        g_off[i] = o;
        g_cur[i] = o;
        int d = g_cnt[i];
        g_dinv[i] = (d > 0) ? rsqrtf((float)d) : 0.0f;
    }
    if (i == 0) g_off[NN] = EE;
}

__global__ void fill_csr_kernel() {
    int e = blockIdx.x * blockDim.x + threadIdx.x;
    if (e < EE) {
        int pos = atomicAdd(&g_cur[g_col[e]], 1);
        g_csrc[pos] = g_row[e];
        g_eid [pos] = e;
    }
}

// hW = fp16(dinv * w), 8 lanes per node, each lane packs 8 halves
__global__ void convw_kernel(const float4* __restrict__ w) {
    int idx = blockIdx.x * blockDim.x + threadIdx.x;     // < NN*8
    if (idx >= NN * HQ) return;
    int node = idx >> 3;
    int c    = idx & 7;
    float di = g_dinv[node];
    float4 w0 = w[(node << 4) + (c << 1)];
    float4 w1 = w[(node << 4) + (c << 1) + 1];
    float4 lo = make_float4(di*w0.x, di*w0.y, di*w0.z, di*w0.w);
    float4 hi = make_float4(di*w1.x, di*w1.y, di*w1.z, di*w1.w);
    g_hW[idx] = pack_half8(lo, hi);
}

// Hop 1 fused with init: gather fp16 hW; out = a0*w + a1*x; hA = fp16(di*x)
__global__ void hop_first_kernel(const float4* __restrict__ w,
                                 const float* __restrict__ alpha) {
    int idx = blockIdx.x * blockDim.x + threadIdx.x;     // < NN*8
    if (idx >= NN * HQ) return;
    int node = idx >> 3;
    int c    = idx & 7;
    int s    = g_off[node];
    int e    = g_off[node + 1];

    float4 alo = make_float4(0.f,0.f,0.f,0.f);
    float4 ahi = make_float4(0.f,0.f,0.f,0.f);
    for (; s + 1 < e; s += 2) {
        int r0 = g_csrc[s], r1 = g_csrc[s + 1];
        float4 l0, h0, l1, h1;
        unpack_half8(g_hW[(r0 << 3) + c], l0, h0);
        unpack_half8(g_hW[(r1 << 3) + c], l1, h1);
        alo.x += l0.x + l1.x; alo.y += l0.y + l1.y;
        alo.z += l0.z + l1.z; alo.w += l0.w + l1.w;
        ahi.x += h0.x + h1.x; ahi.y += h0.y + h1.y;
        ahi.z += h0.z + h1.z; ahi.w += h0.w + h1.w;
    }
    if (s < e) {
        float4 l0, h0;
        unpack_half8(g_hW[(g_csrc[s] << 3) + c], l0, h0);
        alo.x += l0.x; alo.y += l0.y; alo.z += l0.z; alo.w += l0.w;
        ahi.x += h0.x; ahi.y += h0.y; ahi.z += h0.z; ahi.w += h0.w;
    }

    float di = g_dinv[node];
    float a0 = alpha[0];
    float a1 = alpha[1];
    float4 xlo = make_float4(di*alo.x, di*alo.y, di*alo.z, di*alo.w);
    float4 xhi = make_float4(di*ahi.x, di*ahi.y, di*ahi.z, di*ahi.w);
    int ob = (node << 4) + (c << 1);
    float4 w0 = w[ob], w1 = w[ob + 1];
    g_out[ob]     = make_float4(a0*w0.x + a1*xlo.x, a0*w0.y + a1*xlo.y,
                                a0*w0.z + a1*xlo.z, a0*w0.w + a1*xlo.w);
    g_out[ob + 1] = make_float4(a0*w1.x + a1*xhi.x, a0*w1.y + a1*xhi.y,
                                a0*w1.z + a1*xhi.z, a0*w1.w + a1*xhi.w);
    g_hA[idx] = pack_half8(make_float4(di*xlo.x, di*xlo.y, di*xlo.z, di*xlo.w),
                           make_float4(di*xhi.x, di*xhi.y, di*xhi.z, di*xhi.w));
}

// Hops 2..K: gather fp16 xs; write_next ? xs_dst=fp16(di*x) : hO=fp16(out')
__global__ void hop_kernel(const uint4* __restrict__ xs,
                           uint4* __restrict__ xs_dst,
                           const float* __restrict__ alpha, int k,
                           int write_next) {
    int idx = blockIdx.x * blockDim.x + threadIdx.x;     // < NN*8
    if (idx >= NN * HQ) return;
    int node = idx >> 3;
    int c    = idx & 7;
    int s    = g_off[node];
    int e    = g_off[node + 1];

    float4 alo = make_float4(0.f,0.f,0.f,0.f);
    float4 ahi = make_float4(0.f,0.f,0.f,0.f);
    for (; s + 1 < e; s += 2) {
        int r0 = g_csrc[s], r1 = g_csrc[s + 1];
        float4 l0, h0, l1, h1;
        unpack_half8(xs[(r0 << 3) + c], l0, h0);
        unpack_half8(xs[(r1 << 3) + c], l1, h1);
        alo.x += l0.x + l1.x; alo.y += l0.y + l1.y;
        alo.z += l0.z + l1.z; alo.w += l0.w + l1.w;
        ahi.x += h0.x + h1.x; ahi.y += h0.y + h1.y;
        ahi.z += h0.z + h1.z; ahi.w += h0.w + h1.w;
    }
    if (s < e) {
        float4 l0, h0;
        unpack_half8(xs[(g_csrc[s] << 3) + c], l0, h0);
        alo.x += l0.x; alo.y += l0.y; alo.z += l0.z; alo.w += l0.w;
        ahi.x += h0.x; ahi.y += h0.y; ahi.z += h0.z; ahi.w += h0.w;
    }

    float di = g_dinv[node];
    float a  = alpha[k];
    float4 xlo = make_float4(di*alo.x, di*alo.y, di*alo.z, di*alo.w);
    float4 xhi = make_float4(di*ahi.x, di*ahi.y, di*ahi.z, di*ahi.w);
    int ob = (node << 4) + (c << 1);
    float4 o0 = g_out[ob], o1 = g_out[ob + 1];
    o0.x += a*xlo.x; o0.y += a*xlo.y; o0.z += a*xlo.z; o0.w += a*xlo.w;
    o1.x += a*xhi.x; o1.y += a*xhi.y; o1.z += a*xhi.z; o1.w += a*xhi.w;
    g_out[ob] = o0;
    g_out[ob + 1] = o1;
    if (write_next)
        xs_dst[idx] = pack_half8(
            make_float4(di*xlo.x, di*xlo.y, di*xlo.z, di*xlo.w),
            make_float4(di*xhi.x, di*xhi.y, di*xhi.z, di*xhi.w));
    else
        g_hO[idx] = pack_half8(o0, o1);
}

// CSR dot: 8 lanes per node; oi (f32) in registers, gather fp16 hO rows.
__global__ void dot_csr_kernel(float* __restrict__ res) {
    int idx = blockIdx.x * blockDim.x + threadIdx.x;     // < NN*8
    if (idx >= NN * HQ) return;
    int node = idx >> 3;
    int c    = idx & 7;
    int lane = threadIdx.x & 31;
    unsigned mask = 0xFFu << (lane & 24);                // this 8-lane group

    int ob = (node << 4) + (c << 1);
    float4 oi0 = g_out[ob];
    float4 oi1 = g_out[ob + 1];
    int s = g_off[node];
    int e = g_off[node + 1];
    for (; s < e; ++s) {
        int r   = g_csrc[s];
        int eid = g_eid[s];
        float4 lo, hi;
        unpack_half8(g_hO[(r << 3) + c], lo, hi);
        float p = oi0.x*lo.x + oi0.y*lo.y + oi0.z*lo.z + oi0.w*lo.w
                + oi1.x*hi.x + oi1.y*hi.y + oi1.z*hi.z + oi1.w*hi.w;
        p += __shfl_down_sync(mask, p, 4, 8);
        p += __shfl_down_sync(mask, p, 2, 8);
        p += __shfl_down_sync(mask, p, 1, 8);
        if (c == 0) res[eid] = p;
    }
}

// ---- launch ----
extern "C" void kernel_launch(void* const* d_in, const int* in_sizes, int n_in,
                              void* d_out, int out_size) {
    const void*  ei    = nullptr;
    const float* w     = nullptr;
    const float* alpha = nullptr;
    for (int i = 0; i < n_in; ++i) {
        if (in_sizes[i] == 2 * EE)       ei    = d_in[i];
        else if (in_sizes[i] == NN * DD) w     = (const float*)d_in[i];
        else if (in_sizes[i] == 4)       alpha = (const float*)d_in[i];
    }
    float* res = (float*)d_out;

    void *p_hA, *p_hB;
    cudaGetSymbolAddress(&p_hA, g_hA);
    cudaGetSymbolAddress(&p_hB, g_hB);

    const int T = 256;
    const int gE  = (EE + T - 1) / T;
    const int gN  = (NN + T - 1) / T;
    const int gN8 = (NN * HQ + T - 1) / T;   // 3125

    prep0_kernel<<<gN, T>>>((const int*)ei);
    prep_edges_kernel<<<gE, T>>>(ei);
    scan1_kernel<<<NBLK, SBS>>>();
    scan2_kernel<<<NBLK, SBS>>>();
    fill_csr_kernel<<<gE, T>>>();
    convw_kernel<<<gN8, T>>>((const float4*)w);

    uint4* hA = (uint4*)p_hA;
    uint4* hB = (uint4*)p_hB;

    hop_first_kernel<<<gN8, T>>>((const float4*)w, alpha);   // k=1 -> hA
    hop_kernel<<<gN8, T>>>(hA, hB, alpha, 2, 1);             // k=2 -> hB
    hop_kernel<<<gN8, T>>>(hB, hA, alpha, 3, 0);             // k=3 -> g_hO

    dot_csr_kernel<<<gN8, T>>>(res);
}

// round 10
// speedup vs baseline: 4.2824x; 1.0323x over previous
#include <cuda_runtime.h>
#include <cuda_fp16.h>

#define NN 100000
#define EE 1200000
#define DD 64
#define DV (DD/4)        // 16 float4 per node row (f32)
#define HQ 8             // 8 uint4 per node row (fp16: 8 halves each)
#define SBS 1024
#define NBLK ((NN + SBS - 1) / SBS)   // 98

// ---- scratch (static device globals; no allocation at runtime) ----
__device__ int    g_is64;
__device__ int    g_total;
__device__ int    g_cnt [NN];
__device__ int    g_off [NN + 1];
__device__ int    g_cur [NN];
__device__ float  g_dinv[NN];
__device__ int    g_row [EE];
__device__ int    g_col [EE];
__device__ int    g_csrc[EE];          // CSR: source ids grouped by target
__device__ int    g_eid [EE];          // CSR: original edge id
__device__ uint4  g_hW  [NN * HQ];     // fp16 prescaled dinv*w
__device__ uint4  g_hA  [NN * HQ];     // fp16 xs ping
__device__ uint4  g_hB  [NN * HQ];     // fp16 xs pong
__device__ uint4  g_hO  [NN * HQ];     // fp16 shadow of out (dot gathers)
__device__ float4 g_out [NN * DV];     // f32 out

// ---- helpers ----
__device__ __forceinline__ unsigned h2u(__half2 h) { return *(unsigned*)&h; }
__device__ __forceinline__ __half2 u2h(unsigned u) { return *(__half2*)&u; }

__device__ __forceinline__ uint4 pack_half8(float4 lo, float4 hi) {
    uint4 u;
    u.x = h2u(__floats2half2_rn(lo.x, lo.y));
    u.y = h2u(__floats2half2_rn(lo.z, lo.w));
    u.z = h2u(__floats2half2_rn(hi.x, hi.y));
    u.w = h2u(__floats2half2_rn(hi.z, hi.w));
    return u;
}
__device__ __forceinline__ void unpack_half8(uint4 u, float4& lo, float4& hi) {
    float2 a = __half22float2(u2h(u.x));
    float2 b = __half22float2(u2h(u.y));
    float2 c = __half22float2(u2h(u.z));
    float2 d = __half22float2(u2h(u.w));
    lo = make_float4(a.x, a.y, b.x, b.y);
    hi = make_float4(c.x, c.y, d.x, d.y);
}
#define ACC8(A, B, L, H) \
    A.x += L.x; A.y += L.y; A.z += L.z; A.w += L.w; \
    B.x += H.x; B.y += H.y; B.z += H.z; B.w += H.w;

// ---- kernels ----

__global__ void prep0_kernel(const int* __restrict__ ei32) {
    int n = blockIdx.x * blockDim.x + threadIdx.x;
    if (n < NN) g_cnt[n] = 0;
    if (blockIdx.x == 0) {
        if (threadIdx.x == 0) g_total = 0;
        int v = ei32[2 * threadIdx.x + 1];
        int any = __syncthreads_or(v != 0);
        if (threadIdx.x == 0) g_is64 = any ? 0 : 1;
    }
}

__global__ void prep_edges_kernel(const void* __restrict__ ei) {
    int e = blockIdx.x * blockDim.x + threadIdx.x;
    if (e < EE) {
        int r, c;
        if (g_is64) {
            const long long* p = (const long long*)ei;
            r = (int)p[e];
            c = (int)p[EE + e];
        } else {
            const int* p = (const int*)ei;
            r = p[e];
            c = p[EE + e];
        }
        if ((unsigned)r >= NN) r = 0;
        if ((unsigned)c >= NN) c = 0;
        g_row[e] = r;
        g_col[e] = c;
        atomicAdd(&g_cnt[c], 1);
    }
}

// Single-kernel segment allocation: block-local shuffle scan, block base via
// one atomicAdd per block. Segment order across blocks is arbitrary but
// consistent; also computes dinv and cursor init.
__global__ void scan_kernel() {
    __shared__ int wsum[32];
    __shared__ int base;
    int t    = threadIdx.x;
    int lane = t & 31;
    int warp = t >> 5;
    int i = blockIdx.x * SBS + t;
    int v = (i < NN) ? g_cnt[i] : 0;
    int x = v;
    #pragma unroll
    for (int d = 1; d < 32; d <<= 1) {
        int y = __shfl_up_sync(0xFFFFFFFFu, x, d);
        if (lane >= d) x += y;
    }
    if (lane == 31) wsum[warp] = x;
    __syncthreads();
    if (warp == 0) {
        int s = wsum[lane];
        #pragma unroll
        for (int d = 1; d < 32; d <<= 1) {
            int y = __shfl_up_sync(0xFFFFFFFFu, s, d);
            if (lane >= d) s += y;
        }
        wsum[lane] = s;
        if (lane == 31) base = atomicAdd(&g_total, s);
    }
    __syncthreads();
    int excl = x - v + ((warp > 0) ? wsum[warp - 1] : 0) + base;
    if (i < NN) {
        g_off[i] = excl;            // segment start for node i
        g_cur[i] = excl;
        g_dinv[i] = (v > 0) ? rsqrtf((float)v) : 0.0f;
    }
}

__global__ void fill_csr_kernel() {
    int e = blockIdx.x * blockDim.x + threadIdx.x;
    if (e < EE) {
        int pos = atomicAdd(&g_cur[g_col[e]], 1);
        g_csrc[pos] = g_row[e];
        g_eid [pos] = e;
    }
}

// hW = fp16(dinv * w)
__global__ void convw_kernel(const float4* __restrict__ w) {
    int idx = blockIdx.x * blockDim.x + threadIdx.x;     // < NN*8
    if (idx >= NN * HQ) return;
    int node = idx >> 3;
    int c    = idx & 7;
    float di = g_dinv[node];
    float4 w0 = w[(node << 4) + (c << 1)];
    float4 w1 = w[(node << 4) + (c << 1) + 1];
    g_hW[idx] = pack_half8(make_float4(di*w0.x, di*w0.y, di*w0.z, di*w0.w),
                           make_float4(di*w1.x, di*w1.y, di*w1.z, di*w1.w));
}

// Generic fp16 gather loop: unroll-4, two independent accumulator pairs.
__device__ __forceinline__ void gather_seg(const uint4* __restrict__ xs,
                                           int s, int e, int c,
                                           float4& alo, float4& ahi) {
    float4 blo = make_float4(0.f,0.f,0.f,0.f);
    float4 bhi = make_float4(0.f,0.f,0.f,0.f);
    for (; s + 3 < e; s += 4) {
        int r0 = g_csrc[s],     r1 = g_csrc[s + 1];
        int r2 = g_csrc[s + 2], r3 = g_csrc[s + 3];
        uint4 u0 = xs[(r0 << 3) + c];
        uint4 u1 = xs[(r1 << 3) + c];
        uint4 u2 = xs[(r2 << 3) + c];
        uint4 u3 = xs[(r3 << 3) + c];
        float4 l, h;
        unpack_half8(u0, l, h); ACC8(alo, ahi, l, h);
        unpack_half8(u1, l, h); ACC8(blo, bhi, l, h);
        unpack_half8(u2, l, h); ACC8(alo, ahi, l, h);
        unpack_half8(u3, l, h); ACC8(blo, bhi, l, h);
    }
    for (; s < e; ++s) {
        float4 l, h;
        unpack_half8(xs[(g_csrc[s] << 3) + c], l, h);
        ACC8(alo, ahi, l, h);
    }
    ACC8(alo, ahi, blo, bhi);
}

// Hop 1 fused with init: gather fp16 hW; out = a0*w + a1*x; hA = fp16(di*x)
__global__ void hop_first_kernel(const float4* __restrict__ w,
                                 const float* __restrict__ alpha) {
    int idx = blockIdx.x * blockDim.x + threadIdx.x;     // < NN*8
    if (idx >= NN * HQ) return;
    int node = idx >> 3;
    int c    = idx & 7;

    float4 alo = make_float4(0.f,0.f,0.f,0.f);
    float4 ahi = make_float4(0.f,0.f,0.f,0.f);
    gather_seg(g_hW, g_off[node], g_cur[node], c, alo, ahi);

    float di = g_dinv[node];
    float a0 = alpha[0];
    float a1 = alpha[1];
    float4 xlo = make_float4(di*alo.x, di*alo.y, di*alo.z, di*alo.w);
    float4 xhi = make_float4(di*ahi.x, di*ahi.y, di*ahi.z, di*ahi.w);
    int ob = (node << 4) + (c << 1);
    float4 w0 = w[ob], w1 = w[ob + 1];
    g_out[ob]     = make_float4(a0*w0.x + a1*xlo.x, a0*w0.y + a1*xlo.y,
                                a0*w0.z + a1*xlo.z, a0*w0.w + a1*xlo.w);
    g_out[ob + 1] = make_float4(a0*w1.x + a1*xhi.x, a0*w1.y + a1*xhi.y,
                                a0*w1.z + a1*xhi.z, a0*w1.w + a1*xhi.w);
    g_hA[idx] = pack_half8(make_float4(di*xlo.x, di*xlo.y, di*xlo.z, di*xlo.w),
                           make_float4(di*xhi.x, di*xhi.y, di*xhi.z, di*xhi.w));
}

// Hops 2..K
__global__ void hop_kernel(const uint4* __restrict__ xs,
                           uint4* __restrict__ xs_dst,
                           const float* __restrict__ alpha, int k,
                           int write_next) {
    int idx = blockIdx.x * blockDim.x + threadIdx.x;     // < NN*8
    if (idx >= NN * HQ) return;
    int node = idx >> 3;
    int c    = idx & 7;

    float4 alo = make_float4(0.f,0.f,0.f,0.f);
    float4 ahi = make_float4(0.f,0.f,0.f,0.f);
    gather_seg(xs, g_off[node], g_cur[node], c, alo, ahi);

    float di = g_dinv[node];
    float a  = alpha[k];
    float4 xlo = make_float4(di*alo.x, di*alo.y, di*alo.z, di*alo.w);
    float4 xhi = make_float4(di*ahi.x, di*ahi.y, di*ahi.z, di*ahi.w);
    int ob = (node << 4) + (c << 1);
    float4 o0 = g_out[ob], o1 = g_out[ob + 1];
    o0.x += a*xlo.x; o0.y += a*xlo.y; o0.z += a*xlo.z; o0.w += a*xlo.w;
    o1.x += a*xhi.x; o1.y += a*xhi.y; o1.z += a*xhi.z; o1.w += a*xhi.w;
    g_out[ob] = o0;
    g_out[ob + 1] = o1;
    if (write_next)
        xs_dst[idx] = pack_half8(
            make_float4(di*xlo.x, di*xlo.y, di*xlo.z, di*xlo.w),
            make_float4(di*xhi.x, di*xhi.y, di*xhi.z, di*xhi.w));
    else
        g_hO[idx] = pack_half8(o0, o1);
}

// CSR dot with software pipelining: prefetch next row while reducing current.
__global__ void dot_csr_kernel(float* __restrict__ res) {
    int idx = blockIdx.x * blockDim.x + threadIdx.x;     // < NN*8
    if (idx >= NN * HQ) return;
    int node = idx >> 3;
    int c    = idx & 7;
    int lane = threadIdx.x & 31;
    unsigned mask = 0xFFu << (lane & 24);                // this 8-lane group

    int ob = (node << 4) + (c << 1);
    float4 oi0 = g_out[ob];
    float4 oi1 = g_out[ob + 1];
    int s = g_off[node];
    int e = g_cur[node];
    if (s >= e) return;

    uint4 u   = g_hO[(g_csrc[s] << 3) + c];
    int  eid  = g_eid[s];
    for (++s; s < e; ++s) {
        uint4 un  = g_hO[(g_csrc[s] << 3) + c];   // prefetch next
        int  eidn = g_eid[s];
        float4 lo, hi;
        unpack_half8(u, lo, hi);
        float p = oi0.x*lo.x + oi0.y*lo.y + oi0.z*lo.z + oi0.w*lo.w
                + oi1.x*hi.x + oi1.y*hi.y + oi1.z*hi.z + oi1.w*hi.w;
        p += __shfl_down_sync(mask, p, 4, 8);
        p += __shfl_down_sync(mask, p, 2, 8);
        p += __shfl_down_sync(mask, p, 1, 8);
        if (c == 0) res[eid] = p;
        u = un; eid = eidn;
    }
    {
        float4 lo, hi;
        unpack_half8(u, lo, hi);
        float p = oi0.x*lo.x + oi0.y*lo.y + oi0.z*lo.z + oi0.w*lo.w
                + oi1.x*hi.x + oi1.y*hi.y + oi1.z*hi.z + oi1.w*hi.w;
        p += __shfl_down_sync(mask, p, 4, 8);
        p += __shfl_down_sync(mask, p, 2, 8);
        p += __shfl_down_sync(mask, p, 1, 8);
        if (c == 0) res[eid] = p;
    }
}

// ---- launch ----
extern "C" void kernel_launch(void* const* d_in, const int* in_sizes, int n_in,
                              void* d_out, int out_size) {
    const void*  ei    = nullptr;
    const float* w     = nullptr;
    const float* alpha = nullptr;
    for (int i = 0; i < n_in; ++i) {
        if (in_sizes[i] == 2 * EE)       ei    = d_in[i];
        else if (in_sizes[i] == NN * DD) w     = (const float*)d_in[i];
        else if (in_sizes[i] == 4)       alpha = (const float*)d_in[i];
    }
    float* res = (float*)d_out;

    void *p_hA, *p_hB;
    cudaGetSymbolAddress(&p_hA, g_hA);
    cudaGetSymbolAddress(&p_hB, g_hB);

    const int T = 256;
    const int gE  = (EE + T - 1) / T;
    const int gN  = (NN + T - 1) / T;
    const int gN8 = (NN * HQ + T - 1) / T;   // 3125

    prep0_kernel<<<gN, T>>>((const int*)ei);
    prep_edges_kernel<<<gE, T>>>(ei);
    scan_kernel<<<NBLK, SBS>>>();
    fill_csr_kernel<<<gE, T>>>();
    convw_kernel<<<gN8, T>>>((const float4*)w);

    uint4* hA = (uint4*)p_hA;
    uint4* hB = (uint4*)p_hB;

    hop_first_kernel<<<gN8, T>>>((const float4*)w, alpha);   // k=1 -> hA
    hop_kernel<<<gN8, T>>>(hA, hB, alpha, 2, 1);             // k=2 -> hB
    hop_kernel<<<gN8, T>>>(hB, hA, alpha, 3, 0);             // k=3 -> g_hO

    dot_csr_kernel<<<gN8, T>>>(res);
}

// round 11
// speedup vs baseline: 4.4021x; 1.0279x over previous
#include <cuda_runtime.h>
#include <cuda_fp16.h>

#define NN 100000
#define EE 1200000
#define DD 64
#define DV (DD/4)        // 16 float4 per node row (f32)
#define HQ 8             // 8 uint4 per node row (fp16: 8 halves each)
#define SBS 1024
#define NBLK ((NN + SBS - 1) / SBS)   // 98

// ---- scratch (static device globals; no allocation at runtime) ----
__device__ int    g_is64;
__device__ int    g_total;
__device__ int    g_cnt [NN];
__device__ int    g_off [NN];
__device__ int    g_cur [NN];
__device__ float  g_dinv[NN];
__device__ int    g_row [EE];
__device__ int    g_col [EE];
__device__ int2   g_csr [EE];          // CSR entry: {src, original edge id}
__device__ uint4  g_hW  [NN * HQ];     // fp16 prescaled dinv*w
__device__ uint4  g_hA  [NN * HQ];     // fp16 xs ping
__device__ uint4  g_hB  [NN * HQ];     // fp16 xs pong
__device__ uint4  g_hO  [NN * HQ];     // fp16 shadow of out (dot gathers)
__device__ float4 g_out [NN * DV];     // f32 out

// ---- helpers ----
__device__ __forceinline__ unsigned h2u(__half2 h) { return *(unsigned*)&h; }
__device__ __forceinline__ __half2 u2h(unsigned u) { return *(__half2*)&u; }

__device__ __forceinline__ uint4 pack_half8(float4 lo, float4 hi) {
    uint4 u;
    u.x = h2u(__floats2half2_rn(lo.x, lo.y));
    u.y = h2u(__floats2half2_rn(lo.z, lo.w));
    u.z = h2u(__floats2half2_rn(hi.x, hi.y));
    u.w = h2u(__floats2half2_rn(hi.z, hi.w));
    return u;
}
__device__ __forceinline__ void unpack_half8(uint4 u, float4& lo, float4& hi) {
    float2 a = __half22float2(u2h(u.x));
    float2 b = __half22float2(u2h(u.y));
    float2 c = __half22float2(u2h(u.z));
    float2 d = __half22float2(u2h(u.w));
    lo = make_float4(a.x, a.y, b.x, b.y);
    hi = make_float4(c.x, c.y, d.x, d.y);
}
#define ACC8(A, B, L, H) \
    A.x += L.x; A.y += L.y; A.z += L.z; A.w += L.w; \
    B.x += H.x; B.y += H.y; B.z += H.z; B.w += H.w;

// ---- kernels ----

__global__ void prep0_kernel(const int* __restrict__ ei32) {
    int n = blockIdx.x * blockDim.x + threadIdx.x;
    if (n < NN) g_cnt[n] = 0;
    if (blockIdx.x == 0) {
        if (threadIdx.x == 0) g_total = 0;
        int v = ei32[2 * threadIdx.x + 1];
        int any = __syncthreads_or(v != 0);
        if (threadIdx.x == 0) g_is64 = any ? 0 : 1;
    }
}

__global__ void prep_edges_kernel(const void* __restrict__ ei) {
    int e = blockIdx.x * blockDim.x + threadIdx.x;
    if (e < EE) {
        int r, c;
        if (g_is64) {
            const long long* p = (const long long*)ei;
            r = (int)p[e];
            c = (int)p[EE + e];
        } else {
            const int* p = (const int*)ei;
            r = p[e];
            c = p[EE + e];
        }
        if ((unsigned)r >= NN) r = 0;
        if ((unsigned)c >= NN) c = 0;
        g_row[e] = r;
        g_col[e] = c;
        atomicAdd(&g_cnt[c], 1);
    }
}

// Single-kernel segment allocation: block-local shuffle scan, block base via
// one atomicAdd. Segment order across blocks is arbitrary but consistent.
__global__ void scan_kernel() {
    __shared__ int wsum[32];
    __shared__ int base;
    int t    = threadIdx.x;
    int lane = t & 31;
    int warp = t >> 5;
    int i = blockIdx.x * SBS + t;
    int v = (i < NN) ? g_cnt[i] : 0;
    int x = v;
    #pragma unroll
    for (int d = 1; d < 32; d <<= 1) {
        int y = __shfl_up_sync(0xFFFFFFFFu, x, d);
        if (lane >= d) x += y;
    }
    if (lane == 31) wsum[warp] = x;
    __syncthreads();
    if (warp == 0) {
        int s = wsum[lane];
        #pragma unroll
        for (int d = 1; d < 32; d <<= 1) {
            int y = __shfl_up_sync(0xFFFFFFFFu, s, d);
            if (lane >= d) s += y;
        }
        wsum[lane] = s;
        if (lane == 31) base = atomicAdd(&g_total, s);
    }
    __syncthreads();
    int excl = x - v + ((warp > 0) ? wsum[warp - 1] : 0) + base;
    if (i < NN) {
        g_off[i] = excl;            // segment start for node i
        g_cur[i] = excl;
        g_dinv[i] = (v > 0) ? rsqrtf((float)v) : 0.0f;
    }
}

// single STG.64 per edge: {src, eid}
__global__ void fill_csr_kernel() {
    int e = blockIdx.x * blockDim.x + threadIdx.x;
    if (e < EE) {
        int pos = atomicAdd(&g_cur[g_col[e]], 1);
        g_csr[pos] = make_int2(g_row[e], e);
    }
}

// hW = fp16(dinv * w)
__global__ void convw_kernel(const float4* __restrict__ w) {
    int idx = blockIdx.x * blockDim.x + threadIdx.x;     // < NN*8
    if (idx >= NN * HQ) return;
    int node = idx >> 3;
    int c    = idx & 7;
    float di = g_dinv[node];
    float4 w0 = w[(node << 4) + (c << 1)];
    float4 w1 = w[(node << 4) + (c << 1) + 1];
    g_hW[idx] = pack_half8(make_float4(di*w0.x, di*w0.y, di*w0.z, di*w0.w),
                           make_float4(di*w1.x, di*w1.y, di*w1.z, di*w1.w));
}

// Generic fp16 gather loop: unroll-4, two independent accumulator pairs.
__device__ __forceinline__ void gather_seg(const uint4* __restrict__ xs,
                                           int s, int e, int c,
                                           float4& alo, float4& ahi) {
    float4 blo = make_float4(0.f,0.f,0.f,0.f);
    float4 bhi = make_float4(0.f,0.f,0.f,0.f);
    for (; s + 3 < e; s += 4) {
        int r0 = g_csr[s].x,     r1 = g_csr[s + 1].x;
        int r2 = g_csr[s + 2].x, r3 = g_csr[s + 3].x;
        uint4 u0 = xs[(r0 << 3) + c];
        uint4 u1 = xs[(r1 << 3) + c];
        uint4 u2 = xs[(r2 << 3) + c];
        uint4 u3 = xs[(r3 << 3) + c];
        float4 l, h;
        unpack_half8(u0, l, h); ACC8(alo, ahi, l, h);
        unpack_half8(u1, l, h); ACC8(blo, bhi, l, h);
        unpack_half8(u2, l, h); ACC8(alo, ahi, l, h);
        unpack_half8(u3, l, h); ACC8(blo, bhi, l, h);
    }
    for (; s < e; ++s) {
        float4 l, h;
        unpack_half8(xs[(g_csr[s].x << 3) + c], l, h);
        ACC8(alo, ahi, l, h);
    }
    ACC8(alo, ahi, blo, bhi);
}

// Hop 1 fused with init: gather fp16 hW; out = a0*w + a1*x; hA = fp16(di*x)
__global__ void hop_first_kernel(const float4* __restrict__ w,
                                 const float* __restrict__ alpha) {
    int idx = blockIdx.x * blockDim.x + threadIdx.x;     // < NN*8
    if (idx >= NN * HQ) return;
    int node = idx >> 3;
    int c    = idx & 7;

    float4 alo = make_float4(0.f,0.f,0.f,0.f);
    float4 ahi = make_float4(0.f,0.f,0.f,0.f);
    gather_seg(g_hW, g_off[node], g_cur[node], c, alo, ahi);

    float di = g_dinv[node];
    float a0 = alpha[0];
    float a1 = alpha[1];
    float4 xlo = make_float4(di*alo.x, di*alo.y, di*alo.z, di*alo.w);
    float4 xhi = make_float4(di*ahi.x, di*ahi.y, di*ahi.z, di*ahi.w);
    int ob = (node << 4) + (c << 1);
    float4 w0 = w[ob], w1 = w[ob + 1];
    g_out[ob]     = make_float4(a0*w0.x + a1*xlo.x, a0*w0.y + a1*xlo.y,
                                a0*w0.z + a1*xlo.z, a0*w0.w + a1*xlo.w);
    g_out[ob + 1] = make_float4(a0*w1.x + a1*xhi.x, a0*w1.y + a1*xhi.y,
                                a0*w1.z + a1*xhi.z, a0*w1.w + a1*xhi.w);
    g_hA[idx] = pack_half8(make_float4(di*xlo.x, di*xlo.y, di*xlo.z, di*xlo.w),
                           make_float4(di*xhi.x, di*xhi.y, di*xhi.z, di*xhi.w));
}

// Hops 2..K
__global__ void hop_kernel(const uint4* __restrict__ xs,
                           uint4* __restrict__ xs_dst,
                           const float* __restrict__ alpha, int k,
                           int write_next) {
    int idx = blockIdx.x * blockDim.x + threadIdx.x;     // < NN*8
    if (idx >= NN * HQ) return;
    int node = idx >> 3;
    int c    = idx & 7;

    float4 alo = make_float4(0.f,0.f,0.f,0.f);
    float4 ahi = make_float4(0.f,0.f,0.f,0.f);
    gather_seg(xs, g_off[node], g_cur[node], c, alo, ahi);

    float di = g_dinv[node];
    float a  = alpha[k];
    float4 xlo = make_float4(di*alo.x, di*alo.y, di*alo.z, di*alo.w);
    float4 xhi = make_float4(di*ahi.x, di*ahi.y, di*ahi.z, di*ahi.w);
    int ob = (node << 4) + (c << 1);
    float4 o0 = g_out[ob], o1 = g_out[ob + 1];
    o0.x += a*xlo.x; o0.y += a*xlo.y; o0.z += a*xlo.z; o0.w += a*xlo.w;
    o1.x += a*xhi.x; o1.y += a*xhi.y; o1.z += a*xhi.z; o1.w += a*xhi.w;
    g_out[ob] = o0;
    g_out[ob + 1] = o1;
    if (write_next)
        xs_dst[idx] = pack_half8(
            make_float4(di*xlo.x, di*xlo.y, di*xlo.z, di*xlo.w),
            make_float4(di*xhi.x, di*xhi.y, di*xhi.z, di*xhi.w));
    else
        g_hO[idx] = pack_half8(o0, o1);
}

// CSR dot with software pipelining: prefetch next entry while reducing current.
__global__ void dot_csr_kernel(float* __restrict__ res) {
    int idx = blockIdx.x * blockDim.x + threadIdx.x;     // < NN*8
    if (idx >= NN * HQ) return;
    int node = idx >> 3;
    int c    = idx & 7;
    int lane = threadIdx.x & 31;
    unsigned mask = 0xFFu << (lane & 24);                // this 8-lane group

    int ob = (node << 4) + (c << 1);
    float4 oi0 = g_out[ob];
    float4 oi1 = g_out[ob + 1];
    int s = g_off[node];
    int e = g_cur[node];
    if (s >= e) return;

    int2  ce = g_csr[s];
    uint4 u  = g_hO[(ce.x << 3) + c];
    for (++s; s < e; ++s) {
        int2  cen = g_csr[s];
        uint4 un  = g_hO[(cen.x << 3) + c];   // prefetch next
        float4 lo, hi;
        unpack_half8(u, lo, hi);
        float p = oi0.x*lo.x + oi0.y*lo.y + oi0.z*lo.z + oi0.w*lo.w
                + oi1.x*hi.x + oi1.y*hi.y + oi1.z*hi.z + oi1.w*hi.w;
        p += __shfl_down_sync(mask, p, 4, 8);
        p += __shfl_down_sync(mask, p, 2, 8);
        p += __shfl_down_sync(mask, p, 1, 8);
        if (c == 0) res[ce.y] = p;
        ce = cen; u = un;
    }
    {
        float4 lo, hi;
        unpack_half8(u, lo, hi);
        float p = oi0.x*lo.x + oi0.y*lo.y + oi0.z*lo.z + oi0.w*lo.w
                + oi1.x*hi.x + oi1.y*hi.y + oi1.z*hi.z + oi1.w*hi.w;
        p += __shfl_down_sync(mask, p, 4, 8);
        p += __shfl_down_sync(mask, p, 2, 8);
        p += __shfl_down_sync(mask, p, 1, 8);
        if (c == 0) res[ce.y] = p;
    }
}

// ---- launch ----
extern "C" void kernel_launch(void* const* d_in, const int* in_sizes, int n_in,
                              void* d_out, int out_size) {
    const void*  ei    = nullptr;
    const float* w     = nullptr;
    const float* alpha = nullptr;
    for (int i = 0; i < n_in; ++i) {
        if (in_sizes[i] == 2 * EE)       ei    = d_in[i];
        else if (in_sizes[i] == NN * DD) w     = (const float*)d_in[i];
        else if (in_sizes[i] == 4)       alpha = (const float*)d_in[i];
    }
    float* res = (float*)d_out;

    void *p_hA, *p_hB;
    cudaGetSymbolAddress(&p_hA, g_hA);
    cudaGetSymbolAddress(&p_hB, g_hB);

    const int T = 256;
    const int gE  = (EE + T - 1) / T;
    const int gN  = (NN + T - 1) / T;
    const int gN8 = (NN * HQ + T - 1) / T;   // 3125

    prep0_kernel<<<gN, T>>>((const int*)ei);
    prep_edges_kernel<<<gE, T>>>(ei);
    scan_kernel<<<NBLK, SBS>>>();
    fill_csr_kernel<<<gE, T>>>();
    convw_kernel<<<gN8, T>>>((const float4*)w);

    uint4* hA = (uint4*)p_hA;
    uint4* hB = (uint4*)p_hB;

    hop_first_kernel<<<gN8, T>>>((const float4*)w, alpha);   // k=1 -> hA
    hop_kernel<<<gN8, T>>>(hA, hB, alpha, 2, 1);             // k=2 -> hB
    hop_kernel<<<gN8, T>>>(hB, hA, alpha, 3, 0);             // k=3 -> g_hO

    dot_csr_kernel<<<gN8, T>>>(res);
}